// round 12
// baseline (speedup 1.0000x reference)
#include <cuda_runtime.h>
#include <cuda_bf16.h>
#include <cstdint>

#define LRELU_ALPHA 0.2f
#define NROWS 200000
#define IN_F  256
#define OUT_F 128

#define RPB      48                      // rows per CTA (3 mma row-tiles)
#define THREADS  256                     // 8 warps
#define NBLK     ((NROWS + RPB - 1) / RPB)   // 4167

#define PSTRIDE  132                     // u32 (bf16-pairs) per row: 128 + 4 pad
#define AHI_OFF  512                     // after u vectors (512 floats)
#define ALO_OFF  (AHI_OFF + RPB * PSTRIDE)
#define SMEM_U32S (ALO_OFF + RPB * PSTRIDE)
#define SMEM_BYTES (SMEM_U32S * 4)       // 52736 B -> 4 CTAs/SM (206 KB/SM)

__device__ float g_u[2 * IN_F];          // u_top | u_bot
// B fragments, fragment-ordered: [kstep s(16)][ntile(16)][lane(32)] -> {b0,b1}
__device__ uint2 g_Bhi[16 * 16 * 32];
__device__ uint2 g_Blo[16 * 16 * 32];

// ---------------------------------------------------------------------------
__device__ __forceinline__ uint32_t bfpair(float lo_elem, float hi_elem) {
    __nv_bfloat162 h = __floats2bfloat162_rn(lo_elem, hi_elem);
    return *reinterpret_cast<uint32_t*>(&h);
}

// convert two fp32 to (hi bf16-pair, lo bf16-pair) with short live ranges
__device__ __forceinline__ void split2(float a, float b,
                                       uint32_t& hi_out, uint32_t& lo_out) {
    float ha = __bfloat162float(__float2bfloat16_rn(a));
    float hb = __bfloat162float(__float2bfloat16_rn(b));
    hi_out = bfpair(ha, hb);
    lo_out = bfpair(a - ha, b - hb);
}

__device__ __forceinline__ float dot8(float4 x0, float4 x1, float4 y0, float4 y1) {
    float d = 0.f;
    d = fmaf(x0.x, y0.x, d); d = fmaf(x0.y, y0.y, d);
    d = fmaf(x0.z, y0.z, d); d = fmaf(x0.w, y0.w, d);
    d = fmaf(x1.x, y1.x, d); d = fmaf(x1.y, y1.y, d);
    d = fmaf(x1.z, y1.z, d); d = fmaf(x1.w, y1.w, d);
    return d;
}

#define MMA_BF16(d, a, b0v, b1v)                                               \
    asm volatile(                                                              \
        "mma.sync.aligned.m16n8k16.row.col.f32.bf16.bf16.f32 "                 \
        "{%0,%1,%2,%3}, {%4,%5,%6,%7}, {%8,%9}, {%0,%1,%2,%3};"                \
        : "+f"(d[0]), "+f"(d[1]), "+f"(d[2]), "+f"(d[3])                       \
        : "r"(a[0]), "r"(a[1]), "r"(a[2]), "r"(a[3]), "r"(b0v), "r"(b1v))

// ---------------------------------------------------------------------------
// Merged prep kernel: blocks 0..31 compute g_u (one warp per element);
// blocks 32..39 pack W into B-fragment order (each warp does 4 (s,nt) tasks).
// ---------------------------------------------------------------------------
__global__ void prep_kernel(const float* __restrict__ W,
                            const float* __restrict__ s) {
    const int warp = threadIdx.x >> 5;
    const int lane = threadIdx.x & 31;

    if (blockIdx.x < 32) {
        const int gw = blockIdx.x * 8 + warp;  // 0..255 (= i)
        const float* wrow = W + gw * OUT_F;
        float ut = 0.f, ub = 0.f;
#pragma unroll
        for (int jj = 0; jj < 4; ++jj) {
            int j = lane + jj * 32;
            float w = wrow[j];
            ut = fmaf(w, s[j], ut);
            ub = fmaf(w, s[OUT_F + j], ub);
        }
#pragma unroll
        for (int off = 16; off; off >>= 1) {
            ut += __shfl_xor_sync(0xffffffffu, ut, off);
            ub += __shfl_xor_sync(0xffffffffu, ub, off);
        }
        if (lane == 0) {
            g_u[gw] = ut;
            g_u[IN_F + gw] = ub;
        }
    } else {
        const int wtask0 = (blockIdx.x - 32) * 8 + warp;  // 0..63
        const int g = lane >> 2, t = lane & 3;
#pragma unroll
        for (int j = 0; j < 4; ++j) {
            int task = wtask0 + 64 * j;        // 0..255
            int sstep = task >> 4;             // 0..15
            int nt = task & 15;                // 0..15
            int n = nt * 8 + g;
            uint32_t hv[2], lv[2];
#pragma unroll
            for (int rg = 0; rg < 2; ++rg) {
                int k = sstep * 16 + rg * 8 + 2 * t;
                float w0 = W[k * OUT_F + n];
                float w1 = W[(k + 1) * OUT_F + n];
                split2(w0, w1, hv[rg], lv[rg]);
            }
            int idx = (sstep * 16 + nt) * 32 + lane;
            g_Bhi[idx] = make_uint2(hv[0], hv[1]);
            g_Blo[idx] = make_uint2(lv[0], lv[1]);
        }
    }
}

// ---------------------------------------------------------------------------
// Fused kernel: logits -> softmax -> mix (bf16 hi/lo frag layout in smem)
//               -> HMMA GEMM (mix @ W) -> out
// 8 warps/CTA, 4 CTAs/SM (32 warps/SM).
// ---------------------------------------------------------------------------
__global__ __launch_bounds__(THREADS, 4)
void fused_attention_kernel(const float* __restrict__ T,
                            const float* __restrict__ O1,
                            const float* __restrict__ O2,
                            float* __restrict__ out) {
    extern __shared__ char smem_raw[];
    uint32_t* s32 = reinterpret_cast<uint32_t*>(smem_raw);
    float* s_u = reinterpret_cast<float*>(smem_raw);
    uint32_t* smA_hi = s32 + AHI_OFF;
    uint32_t* smA_lo = s32 + ALO_OFF;

    const int tid  = threadIdx.x;
    const int lane = tid & 31;
    const int w    = tid >> 5;    // 0..7
    const int row0 = blockIdx.x * RPB;

    for (int i = tid; i < 2 * IN_F; i += THREADS) s_u[i] = g_u[i];
    __syncthreads();

    // ---------------- Phase 1: 6 rows per warp, one row at a time -----------
    {
        const float4* up = reinterpret_cast<const float4*>(s_u) + lane * 2;
        const float4 ut0 = up[0], ut1 = up[1];
        const float4* bp = reinterpret_cast<const float4*>(s_u + IN_F) + lane * 2;
        const float4 ub0 = bp[0], ub1 = bp[1];

#pragma unroll 1
        for (int rr = 0; rr < 6; ++rr) {
            const int r = w * 6 + rr;
            long long g = (long long)(row0 + r);
            if (g >= NROWS) g = NROWS - 1;

            const float4* tp = reinterpret_cast<const float4*>(T  + g * IN_F) + lane * 2;
            const float4* ap = reinterpret_cast<const float4*>(O1 + g * IN_F) + lane * 2;
            const float4* zp = reinterpret_cast<const float4*>(O2 + g * IN_F) + lane * 2;
            float4 x0 = tp[0], x1 = tp[1];
            float4 y0 = ap[0], y1 = ap[1];
            float4 z0 = zp[0], z1 = zp[1];

            float dtt = dot8(x0, x1, ut0, ut1);
            float dtb = dot8(x0, x1, ub0, ub1);
            float d1v = dot8(y0, y1, ub0, ub1);
            float d2v = dot8(z0, z1, ub0, ub1);
#pragma unroll
            for (int off = 16; off; off >>= 1) {
                dtt += __shfl_xor_sync(0xffffffffu, dtt, off);
                dtb += __shfl_xor_sync(0xffffffffu, dtb, off);
                d1v += __shfl_xor_sync(0xffffffffu, d1v, off);
                d2v += __shfl_xor_sync(0xffffffffu, d2v, off);
            }

            float e0 = dtt + dtb, e1 = dtt + d1v, e2 = dtt + d2v;
            e0 = e0 > 0.f ? e0 : LRELU_ALPHA * e0;
            e1 = e1 > 0.f ? e1 : LRELU_ALPHA * e1;
            e2 = e2 > 0.f ? e2 : LRELU_ALPHA * e2;
            float m = fmaxf(e0, fmaxf(e1, e2));
            float w0 = __expf(e0 - m), w1 = __expf(e1 - m), w2 = __expf(e2 - m);
            float inv = 1.f / (w0 + w1 + w2);
            w0 *= inv; w1 *= inv; w2 *= inv;

            // mix + pairwise bf16 hi/lo split (short live ranges)
            uint4 vh, vl;
            {
                float a = fmaf(w0, x0.x, fmaf(w1, y0.x, w2 * z0.x));
                float b = fmaf(w0, x0.y, fmaf(w1, y0.y, w2 * z0.y));
                split2(a, b, vh.x, vl.x);
            }
            {
                float a = fmaf(w0, x0.z, fmaf(w1, y0.z, w2 * z0.z));
                float b = fmaf(w0, x0.w, fmaf(w1, y0.w, w2 * z0.w));
                split2(a, b, vh.y, vl.y);
            }
            {
                float a = fmaf(w0, x1.x, fmaf(w1, y1.x, w2 * z1.x));
                float b = fmaf(w0, x1.y, fmaf(w1, y1.y, w2 * z1.y));
                split2(a, b, vh.z, vl.z);
            }
            {
                float a = fmaf(w0, x1.z, fmaf(w1, y1.z, w2 * z1.z));
                float b = fmaf(w0, x1.w, fmaf(w1, y1.w, w2 * z1.w));
                split2(a, b, vh.w, vl.w);
            }
            *reinterpret_cast<uint4*>(smA_hi + r * PSTRIDE + lane * 4) = vh;
            *reinterpret_cast<uint4*>(smA_lo + r * PSTRIDE + lane * 4) = vl;
        }
    }
    __syncthreads();

    // ---------------- Phase 2: out[48x128] = mix @ W via HMMA ---------------
    // warp w owns n-tiles {2w, 2w+1} (cols 16w..16w+15); 3 row-tiles of 16.
    {
        const int g = lane >> 2;       // 0..7
        const int t = lane & 3;        // 0..3

        float acc[3][2][4];
#pragma unroll
        for (int r = 0; r < 3; ++r)
#pragma unroll
            for (int c = 0; c < 2; ++c)
#pragma unroll
                for (int i = 0; i < 4; ++i) acc[r][c][i] = 0.f;

#pragma unroll 1
        for (int s = 0; s < 16; ++s) {
            uint32_t ah[3][4], al[3][4];
#pragma unroll
            for (int r = 0; r < 3; ++r) {
                int base = (16 * r + g) * PSTRIDE + 8 * s + t;
                ah[r][0] = smA_hi[base];
                ah[r][1] = smA_hi[base + 8 * PSTRIDE];
                ah[r][2] = smA_hi[base + 4];
                ah[r][3] = smA_hi[base + 8 * PSTRIDE + 4];
                al[r][0] = smA_lo[base];
                al[r][1] = smA_lo[base + 8 * PSTRIDE];
                al[r][2] = smA_lo[base + 4];
                al[r][3] = smA_lo[base + 8 * PSTRIDE + 4];
            }
#pragma unroll
            for (int c = 0; c < 2; ++c) {
                int nt = 2 * w + c;
                uint2 bh = __ldg(&g_Bhi[(s * 16 + nt) * 32 + lane]);
                uint2 bl = __ldg(&g_Blo[(s * 16 + nt) * 32 + lane]);
#pragma unroll
                for (int r = 0; r < 3; ++r) {
                    MMA_BF16(acc[r][c], ah[r], bh.x, bh.y);
                    MMA_BF16(acc[r][c], al[r], bh.x, bh.y);
                    MMA_BF16(acc[r][c], ah[r], bl.x, bl.y);
                }
            }
        }

        // epilogue: d0,d1 -> (row 16r+g, cols 2t,2t+1); d2,d3 -> row +8
#pragma unroll
        for (int r = 0; r < 3; ++r) {
            const long long rowA = (long long)(row0 + 16 * r + g);
            const long long rowB = rowA + 8;
            const bool vA = rowA < NROWS;
            const bool vB = rowB < NROWS;
#pragma unroll
            for (int c = 0; c < 2; ++c) {
                const int col = 8 * (2 * w + c) + 2 * t;
                if (vA) {
                    float2 v0 = make_float2(acc[r][c][0], acc[r][c][1]);
                    *reinterpret_cast<float2*>(out + rowA * OUT_F + col) = v0;
                }
                if (vB) {
                    float2 v1 = make_float2(acc[r][c][2], acc[r][c][3]);
                    *reinterpret_cast<float2*>(out + rowB * OUT_F + col) = v1;
                }
            }
        }
    }
}

// ---------------------------------------------------------------------------
extern "C" void kernel_launch(void* const* d_in, const int* in_sizes, int n_in,
                              void* d_out, int out_size) {
    const float* T  = (const float*)d_in[0];
    const float* O1 = (const float*)d_in[1];
    const float* O2 = (const float*)d_in[2];
    const float* W  = (const float*)d_in[3];
    const float* s  = (const float*)d_in[4];
    float* out = (float*)d_out;

    cudaFuncSetAttribute(fused_attention_kernel,
                         cudaFuncAttributeMaxDynamicSharedMemorySize, SMEM_BYTES);

    prep_kernel<<<40, 256>>>(W, s);
    fused_attention_kernel<<<NBLK, THREADS, SMEM_BYTES>>>(T, O1, O2, out);
}

// round 13
// speedup vs baseline: 1.0961x; 1.0961x over previous
#include <cuda_runtime.h>
#include <cuda_bf16.h>
#include <cstdint>

#define LRELU_ALPHA 0.2f
#define NROWS 200000
#define IN_F  256
#define OUT_F 128

#define RPB      48                      // rows per CTA (3 mma row-tiles)
#define THREADS  256                     // 8 warps
#define NBLK     ((NROWS + RPB - 1) / RPB)   // 4167

#define PSTRIDE  132                     // u32 (bf16-pairs) per row: 128 + 4 pad
#define AHI_OFF  512                     // after u vectors (512 floats)
#define ALO_OFF  (AHI_OFF + RPB * PSTRIDE)
#define SMEM_U32S (ALO_OFF + RPB * PSTRIDE)
#define SMEM_BYTES (SMEM_U32S * 4)       // 52736 B -> 3 CTAs/SM, ~70KB L1D left

__device__ float g_u[2 * IN_F];          // u_top | u_bot
// B fragments, fragment-ordered: [kstep s(16)][ntile(16)][lane(32)] -> {b0,b1}
__device__ uint2 g_Bhi[16 * 16 * 32];
__device__ uint2 g_Blo[16 * 16 * 32];

// ---------------------------------------------------------------------------
__device__ __forceinline__ uint32_t bfpair(float lo_elem, float hi_elem) {
    __nv_bfloat162 h = __floats2bfloat162_rn(lo_elem, hi_elem);
    return *reinterpret_cast<uint32_t*>(&h);
}

// convert two fp32 to (hi bf16-pair, lo bf16-pair)
__device__ __forceinline__ void split2(float a, float b,
                                       uint32_t& hi_out, uint32_t& lo_out) {
    float ha = __bfloat162float(__float2bfloat16_rn(a));
    float hb = __bfloat162float(__float2bfloat16_rn(b));
    hi_out = bfpair(ha, hb);
    lo_out = bfpair(a - ha, b - hb);
}

__device__ __forceinline__ float dot8(float4 x0, float4 x1, float4 y0, float4 y1) {
    float d = 0.f;
    d = fmaf(x0.x, y0.x, d); d = fmaf(x0.y, y0.y, d);
    d = fmaf(x0.z, y0.z, d); d = fmaf(x0.w, y0.w, d);
    d = fmaf(x1.x, y1.x, d); d = fmaf(x1.y, y1.y, d);
    d = fmaf(x1.z, y1.z, d); d = fmaf(x1.w, y1.w, d);
    return d;
}

#define MMA_BF16(d, a, b0v, b1v)                                               \
    asm volatile(                                                              \
        "mma.sync.aligned.m16n8k16.row.col.f32.bf16.bf16.f32 "                 \
        "{%0,%1,%2,%3}, {%4,%5,%6,%7}, {%8,%9}, {%0,%1,%2,%3};"                \
        : "+f"(d[0]), "+f"(d[1]), "+f"(d[2]), "+f"(d[3])                       \
        : "r"(a[0]), "r"(a[1]), "r"(a[2]), "r"(a[3]), "r"(b0v), "r"(b1v))

// one-instruction m16k16 A-fragment load (4x 8x8 b16 tiles)
__device__ __forceinline__ void ldsm_x4(uint32_t (&r)[4], uint32_t saddr) {
    asm volatile(
        "ldmatrix.sync.aligned.m8n8.x4.shared.b16 {%0,%1,%2,%3}, [%4];"
        : "=r"(r[0]), "=r"(r[1]), "=r"(r[2]), "=r"(r[3])
        : "r"(saddr));
}

// ---------------------------------------------------------------------------
// Merged prep kernel: blocks 0..31 compute g_u (one warp per element);
// blocks 32..39 pack W into B-fragment order (each warp does 4 (s,nt) tasks).
// ---------------------------------------------------------------------------
__global__ void prep_kernel(const float* __restrict__ W,
                            const float* __restrict__ s) {
    const int warp = threadIdx.x >> 5;
    const int lane = threadIdx.x & 31;

    if (blockIdx.x < 32) {
        const int gw = blockIdx.x * 8 + warp;  // 0..255 (= i)
        const float* wrow = W + gw * OUT_F;
        float ut = 0.f, ub = 0.f;
#pragma unroll
        for (int jj = 0; jj < 4; ++jj) {
            int j = lane + jj * 32;
            float w = wrow[j];
            ut = fmaf(w, s[j], ut);
            ub = fmaf(w, s[OUT_F + j], ub);
        }
#pragma unroll
        for (int off = 16; off; off >>= 1) {
            ut += __shfl_xor_sync(0xffffffffu, ut, off);
            ub += __shfl_xor_sync(0xffffffffu, ub, off);
        }
        if (lane == 0) {
            g_u[gw] = ut;
            g_u[IN_F + gw] = ub;
        }
    } else {
        const int wtask0 = (blockIdx.x - 32) * 8 + warp;  // 0..63
        const int g = lane >> 2, t = lane & 3;
#pragma unroll
        for (int j = 0; j < 4; ++j) {
            int task = wtask0 + 64 * j;        // 0..255
            int sstep = task >> 4;             // 0..15
            int nt = task & 15;                // 0..15
            int n = nt * 8 + g;
            uint32_t hv[2], lv[2];
#pragma unroll
            for (int rg = 0; rg < 2; ++rg) {
                int k = sstep * 16 + rg * 8 + 2 * t;
                float w0 = W[k * OUT_F + n];
                float w1 = W[(k + 1) * OUT_F + n];
                split2(w0, w1, hv[rg], lv[rg]);
            }
            int idx = (sstep * 16 + nt) * 32 + lane;
            g_Bhi[idx] = make_uint2(hv[0], hv[1]);
            g_Blo[idx] = make_uint2(lv[0], lv[1]);
        }
    }
}

// ---------------------------------------------------------------------------
// Fused kernel: logits -> softmax -> mix (bf16 hi/lo frag layout in smem)
//               -> HMMA GEMM (mix @ W) -> out
// 8 warps/CTA, 3 CTAs/SM. Phase-2 A-fragments via ldmatrix.x4.
// ---------------------------------------------------------------------------
__global__ __launch_bounds__(THREADS, 3)
void fused_attention_kernel(const float* __restrict__ T,
                            const float* __restrict__ O1,
                            const float* __restrict__ O2,
                            float* __restrict__ out) {
    extern __shared__ char smem_raw[];
    uint32_t* s32 = reinterpret_cast<uint32_t*>(smem_raw);
    float* s_u = reinterpret_cast<float*>(smem_raw);
    uint32_t* smA_hi = s32 + AHI_OFF;
    uint32_t* smA_lo = s32 + ALO_OFF;

    const int tid  = threadIdx.x;
    const int lane = tid & 31;
    const int w    = tid >> 5;    // 0..7
    const int row0 = blockIdx.x * RPB;

    for (int i = tid; i < 2 * IN_F; i += THREADS) s_u[i] = g_u[i];
    __syncthreads();

    // ---------------- Phase 1: 6 rows per warp, one row at a time -----------
    {
        const float4* up = reinterpret_cast<const float4*>(s_u) + lane * 2;
        const float4 ut0 = up[0], ut1 = up[1];
        const float4* bp = reinterpret_cast<const float4*>(s_u + IN_F) + lane * 2;
        const float4 ub0 = bp[0], ub1 = bp[1];

#pragma unroll 1
        for (int rr = 0; rr < 6; ++rr) {
            const int r = w * 6 + rr;
            long long g = (long long)(row0 + r);
            if (g >= NROWS) g = NROWS - 1;

            const float4* tp = reinterpret_cast<const float4*>(T  + g * IN_F) + lane * 2;
            const float4* ap = reinterpret_cast<const float4*>(O1 + g * IN_F) + lane * 2;
            const float4* zp = reinterpret_cast<const float4*>(O2 + g * IN_F) + lane * 2;
            float4 x0 = tp[0], x1 = tp[1];
            float4 y0 = ap[0], y1 = ap[1];
            float4 z0 = zp[0], z1 = zp[1];

            float dtt = dot8(x0, x1, ut0, ut1);
            float dtb = dot8(x0, x1, ub0, ub1);
            float d1v = dot8(y0, y1, ub0, ub1);
            float d2v = dot8(z0, z1, ub0, ub1);
#pragma unroll
            for (int off = 16; off; off >>= 1) {
                dtt += __shfl_xor_sync(0xffffffffu, dtt, off);
                dtb += __shfl_xor_sync(0xffffffffu, dtb, off);
                d1v += __shfl_xor_sync(0xffffffffu, d1v, off);
                d2v += __shfl_xor_sync(0xffffffffu, d2v, off);
            }

            float e0 = dtt + dtb, e1 = dtt + d1v, e2 = dtt + d2v;
            e0 = e0 > 0.f ? e0 : LRELU_ALPHA * e0;
            e1 = e1 > 0.f ? e1 : LRELU_ALPHA * e1;
            e2 = e2 > 0.f ? e2 : LRELU_ALPHA * e2;
            float m = fmaxf(e0, fmaxf(e1, e2));
            float w0 = __expf(e0 - m), w1 = __expf(e1 - m), w2 = __expf(e2 - m);
            float inv = 1.f / (w0 + w1 + w2);
            w0 *= inv; w1 *= inv; w2 *= inv;

            uint4 vh, vl;
            {
                float a = fmaf(w0, x0.x, fmaf(w1, y0.x, w2 * z0.x));
                float b = fmaf(w0, x0.y, fmaf(w1, y0.y, w2 * z0.y));
                split2(a, b, vh.x, vl.x);
            }
            {
                float a = fmaf(w0, x0.z, fmaf(w1, y0.z, w2 * z0.z));
                float b = fmaf(w0, x0.w, fmaf(w1, y0.w, w2 * z0.w));
                split2(a, b, vh.y, vl.y);
            }
            {
                float a = fmaf(w0, x1.x, fmaf(w1, y1.x, w2 * z1.x));
                float b = fmaf(w0, x1.y, fmaf(w1, y1.y, w2 * z1.y));
                split2(a, b, vh.z, vl.z);
            }
            {
                float a = fmaf(w0, x1.z, fmaf(w1, y1.z, w2 * z1.z));
                float b = fmaf(w0, x1.w, fmaf(w1, y1.w, w2 * z1.w));
                split2(a, b, vh.w, vl.w);
            }
            *reinterpret_cast<uint4*>(smA_hi + r * PSTRIDE + lane * 4) = vh;
            *reinterpret_cast<uint4*>(smA_lo + r * PSTRIDE + lane * 4) = vl;
        }
    }
    __syncthreads();

    // ---------------- Phase 2: out[48x128] = mix @ W via HMMA + LDSM --------
    // warp w owns n-tiles {2w, 2w+1} (cols 16w..16w+15); 3 row-tiles of 16.
    {
        const int g = lane >> 2;       // 0..7
        const int t = lane & 3;        // 0..3

        // ldmatrix lane addressing: row = lane&15 within tile, k-half = lane>>4
        const uint32_t a_base =
            (uint32_t)__cvta_generic_to_shared(smA_hi);
        const uint32_t l_base =
            (uint32_t)__cvta_generic_to_shared(smA_lo);
        const uint32_t lane_off =
            (uint32_t)((lane & 15) * PSTRIDE + 4 * (lane >> 4));  // u32 units

        float acc[3][2][4];
#pragma unroll
        for (int r = 0; r < 3; ++r)
#pragma unroll
            for (int c = 0; c < 2; ++c)
#pragma unroll
                for (int i = 0; i < 4; ++i) acc[r][c][i] = 0.f;

#pragma unroll 1
        for (int s = 0; s < 16; ++s) {
            uint32_t ah[3][4], al[3][4];
#pragma unroll
            for (int r = 0; r < 3; ++r) {
                uint32_t off = 4u * (16u * r * PSTRIDE + lane_off + 8u * s);
                ldsm_x4(ah[r], a_base + off);
                ldsm_x4(al[r], l_base + off);
            }
#pragma unroll
            for (int c = 0; c < 2; ++c) {
                int nt = 2 * w + c;
                uint2 bh = __ldg(&g_Bhi[(s * 16 + nt) * 32 + lane]);
                uint2 bl = __ldg(&g_Blo[(s * 16 + nt) * 32 + lane]);
#pragma unroll
                for (int r = 0; r < 3; ++r) {
                    MMA_BF16(acc[r][c], ah[r], bh.x, bh.y);
                    MMA_BF16(acc[r][c], al[r], bh.x, bh.y);
                    MMA_BF16(acc[r][c], ah[r], bl.x, bl.y);
                }
            }
        }

        // epilogue: d0,d1 -> (row 16r+g, cols 2t,2t+1); d2,d3 -> row +8
#pragma unroll
        for (int r = 0; r < 3; ++r) {
            const long long rowA = (long long)(row0 + 16 * r + g);
            const long long rowB = rowA + 8;
            const bool vA = rowA < NROWS;
            const bool vB = rowB < NROWS;
#pragma unroll
            for (int c = 0; c < 2; ++c) {
                const int col = 8 * (2 * w + c) + 2 * t;
                if (vA) {
                    float2 v0 = make_float2(acc[r][c][0], acc[r][c][1]);
                    *reinterpret_cast<float2*>(out + rowA * OUT_F + col) = v0;
                }
                if (vB) {
                    float2 v1 = make_float2(acc[r][c][2], acc[r][c][3]);
                    *reinterpret_cast<float2*>(out + rowB * OUT_F + col) = v1;
                }
            }
        }
    }
}

// ---------------------------------------------------------------------------
extern "C" void kernel_launch(void* const* d_in, const int* in_sizes, int n_in,
                              void* d_out, int out_size) {
    const float* T  = (const float*)d_in[0];
    const float* O1 = (const float*)d_in[1];
    const float* O2 = (const float*)d_in[2];
    const float* W  = (const float*)d_in[3];
    const float* s  = (const float*)d_in[4];
    float* out = (float*)d_out;

    cudaFuncSetAttribute(fused_attention_kernel,
                         cudaFuncAttributeMaxDynamicSharedMemorySize, SMEM_BYTES);

    prep_kernel<<<40, 256>>>(W, s);
    fused_attention_kernel<<<NBLK, THREADS, SMEM_BYTES>>>(T, O1, O2, out);
}

// round 14
// speedup vs baseline: 1.0984x; 1.0021x over previous
#include <cuda_runtime.h>
#include <cuda_bf16.h>
#include <cstdint>

#define LRELU_ALPHA 0.2f
#define NROWS 200000
#define IN_F  256
#define OUT_F 128

#define RPB      48                      // rows per CTA (3 mma row-tiles)
#define THREADS  256                     // 8 warps
#define NBLK     ((NROWS + RPB - 1) / RPB)   // 4167

#define PSTRIDE  132                     // u32 (bf16-pairs) per row: 128 + 4 pad
#define AHI_OFF  512                     // after u vectors (512 floats)
#define ALO_OFF  (AHI_OFF + RPB * PSTRIDE)
#define SMEM_U32S (ALO_OFF + RPB * PSTRIDE)
#define SMEM_BYTES (SMEM_U32S * 4)       // 52736 B -> 3 CTAs/SM, ~70KB L1D left

__device__ float g_u[2 * IN_F];          // u_top | u_bot
// B fragments, fragment-ordered: [kstep s(16)][ntile(16)][lane(32)] -> {b0,b1}
__device__ uint2 g_Bhi[16 * 16 * 32];
__device__ uint2 g_Blo[16 * 16 * 32];

// ---------------------------------------------------------------------------
__device__ __forceinline__ uint32_t bfpair(float lo_elem, float hi_elem) {
    __nv_bfloat162 h = __floats2bfloat162_rn(lo_elem, hi_elem);
    return *reinterpret_cast<uint32_t*>(&h);
}

// convert two fp32 to (hi bf16-pair, lo bf16-pair)
__device__ __forceinline__ void split2(float a, float b,
                                       uint32_t& hi_out, uint32_t& lo_out) {
    float ha = __bfloat162float(__float2bfloat16_rn(a));
    float hb = __bfloat162float(__float2bfloat16_rn(b));
    hi_out = bfpair(ha, hb);
    lo_out = bfpair(a - ha, b - hb);
}

__device__ __forceinline__ float dot8(float4 x0, float4 x1, float4 y0, float4 y1) {
    float d = 0.f;
    d = fmaf(x0.x, y0.x, d); d = fmaf(x0.y, y0.y, d);
    d = fmaf(x0.z, y0.z, d); d = fmaf(x0.w, y0.w, d);
    d = fmaf(x1.x, y1.x, d); d = fmaf(x1.y, y1.y, d);
    d = fmaf(x1.z, y1.z, d); d = fmaf(x1.w, y1.w, d);
    return d;
}

#define MMA_BF16(d, a, b0v, b1v)                                               \
    asm volatile(                                                              \
        "mma.sync.aligned.m16n8k16.row.col.f32.bf16.bf16.f32 "                 \
        "{%0,%1,%2,%3}, {%4,%5,%6,%7}, {%8,%9}, {%0,%1,%2,%3};"                \
        : "+f"(d[0]), "+f"(d[1]), "+f"(d[2]), "+f"(d[3])                       \
        : "r"(a[0]), "r"(a[1]), "r"(a[2]), "r"(a[3]), "r"(b0v), "r"(b1v))

// one-instruction m16k16 A-fragment load (4x 8x8 b16 tiles)
__device__ __forceinline__ void ldsm_x4(uint32_t (&r)[4], uint32_t saddr) {
    asm volatile(
        "ldmatrix.sync.aligned.m8n8.x4.shared.b16 {%0,%1,%2,%3}, [%4];"
        : "=r"(r[0]), "=r"(r[1]), "=r"(r[2]), "=r"(r[3])
        : "r"(saddr));
}

// ---------------------------------------------------------------------------
// Merged prep kernel: blocks 0..31 compute g_u (one warp per element);
// blocks 32..39 pack W into B-fragment order (each warp does 4 (s,nt) tasks).
// ---------------------------------------------------------------------------
__global__ void prep_kernel(const float* __restrict__ W,
                            const float* __restrict__ s) {
    const int warp = threadIdx.x >> 5;
    const int lane = threadIdx.x & 31;

    if (blockIdx.x < 32) {
        const int gw = blockIdx.x * 8 + warp;  // 0..255 (= i)
        const float* wrow = W + gw * OUT_F;
        float ut = 0.f, ub = 0.f;
#pragma unroll
        for (int jj = 0; jj < 4; ++jj) {
            int j = lane + jj * 32;
            float w = wrow[j];
            ut = fmaf(w, s[j], ut);
            ub = fmaf(w, s[OUT_F + j], ub);
        }
#pragma unroll
        for (int off = 16; off; off >>= 1) {
            ut += __shfl_xor_sync(0xffffffffu, ut, off);
            ub += __shfl_xor_sync(0xffffffffu, ub, off);
        }
        if (lane == 0) {
            g_u[gw] = ut;
            g_u[IN_F + gw] = ub;
        }
    } else {
        const int wtask0 = (blockIdx.x - 32) * 8 + warp;  // 0..63
        const int g = lane >> 2, t = lane & 3;
#pragma unroll
        for (int j = 0; j < 4; ++j) {
            int task = wtask0 + 64 * j;        // 0..255
            int sstep = task >> 4;             // 0..15
            int nt = task & 15;                // 0..15
            int n = nt * 8 + g;
            uint32_t hv[2], lv[2];
#pragma unroll
            for (int rg = 0; rg < 2; ++rg) {
                int k = sstep * 16 + rg * 8 + 2 * t;
                float w0 = W[k * OUT_F + n];
                float w1 = W[(k + 1) * OUT_F + n];
                split2(w0, w1, hv[rg], lv[rg]);
            }
            int idx = (sstep * 16 + nt) * 32 + lane;
            g_Bhi[idx] = make_uint2(hv[0], hv[1]);
            g_Blo[idx] = make_uint2(lv[0], lv[1]);
        }
    }
}

// ---------------------------------------------------------------------------
// Fused kernel: logits -> softmax -> mix (bf16 hi/lo frag layout in smem)
//               -> HMMA GEMM (mix @ W) -> out
// 8 warps/CTA, 3 CTAs/SM. Phase-1 x-row prefetch; phase-2 LDSM + B prefetch.
// ---------------------------------------------------------------------------
__global__ __launch_bounds__(THREADS, 3)
void fused_attention_kernel(const float* __restrict__ T,
                            const float* __restrict__ O1,
                            const float* __restrict__ O2,
                            float* __restrict__ out) {
    extern __shared__ char smem_raw[];
    uint32_t* s32 = reinterpret_cast<uint32_t*>(smem_raw);
    float* s_u = reinterpret_cast<float*>(smem_raw);
    uint32_t* smA_hi = s32 + AHI_OFF;
    uint32_t* smA_lo = s32 + ALO_OFF;

    const int tid  = threadIdx.x;
    const int lane = tid & 31;
    const int w    = tid >> 5;    // 0..7
    const int row0 = blockIdx.x * RPB;

    for (int i = tid; i < 2 * IN_F; i += THREADS) s_u[i] = g_u[i];
    __syncthreads();

    // ---------------- Phase 1: 6 rows per warp, x-row prefetched ------------
    {
        const float4* up = reinterpret_cast<const float4*>(s_u) + lane * 2;
        const float4 ut0 = up[0], ut1 = up[1];
        const float4* bp = reinterpret_cast<const float4*>(s_u + IN_F) + lane * 2;
        const float4 ub0 = bp[0], ub1 = bp[1];

        const int rbase = w * 6;

        // preload x (T row) for rr = 0
        float4 x0, x1;
        {
            long long g = (long long)(row0 + rbase);
            if (g >= NROWS) g = NROWS - 1;
            const float4* tp = reinterpret_cast<const float4*>(T + g * IN_F) + lane * 2;
            x0 = tp[0]; x1 = tp[1];
        }

#pragma unroll 1
        for (int rr = 0; rr < 6; ++rr) {
            const int r = rbase + rr;
            long long g = (long long)(row0 + r);
            if (g >= NROWS) g = NROWS - 1;

            // issue y/z loads for this row
            const float4* ap = reinterpret_cast<const float4*>(O1 + g * IN_F) + lane * 2;
            const float4* zp = reinterpret_cast<const float4*>(O2 + g * IN_F) + lane * 2;
            float4 y0 = ap[0], y1 = ap[1];
            float4 z0 = zp[0], z1 = zp[1];

            // prefetch next row's x while we chew on this row
            float4 nx0 = x0, nx1 = x1;
            if (rr < 5) {
                long long gn = (long long)(row0 + r + 1);
                if (gn >= NROWS) gn = NROWS - 1;
                const float4* tn = reinterpret_cast<const float4*>(T + gn * IN_F) + lane * 2;
                nx0 = tn[0]; nx1 = tn[1];
            }

            // x-dots first (x already resident), y/z dots as they arrive
            float dtt = dot8(x0, x1, ut0, ut1);
            float dtb = dot8(x0, x1, ub0, ub1);
            float d1v = dot8(y0, y1, ub0, ub1);
            float d2v = dot8(z0, z1, ub0, ub1);
#pragma unroll
            for (int off = 16; off; off >>= 1) {
                dtt += __shfl_xor_sync(0xffffffffu, dtt, off);
                dtb += __shfl_xor_sync(0xffffffffu, dtb, off);
                d1v += __shfl_xor_sync(0xffffffffu, d1v, off);
                d2v += __shfl_xor_sync(0xffffffffu, d2v, off);
            }

            float e0 = dtt + dtb, e1 = dtt + d1v, e2 = dtt + d2v;
            e0 = e0 > 0.f ? e0 : LRELU_ALPHA * e0;
            e1 = e1 > 0.f ? e1 : LRELU_ALPHA * e1;
            e2 = e2 > 0.f ? e2 : LRELU_ALPHA * e2;
            float m = fmaxf(e0, fmaxf(e1, e2));
            float w0 = __expf(e0 - m), w1 = __expf(e1 - m), w2 = __expf(e2 - m);
            float inv = 1.f / (w0 + w1 + w2);
            w0 *= inv; w1 *= inv; w2 *= inv;

            uint4 vh, vl;
            {
                float a = fmaf(w0, x0.x, fmaf(w1, y0.x, w2 * z0.x));
                float b = fmaf(w0, x0.y, fmaf(w1, y0.y, w2 * z0.y));
                split2(a, b, vh.x, vl.x);
            }
            {
                float a = fmaf(w0, x0.z, fmaf(w1, y0.z, w2 * z0.z));
                float b = fmaf(w0, x0.w, fmaf(w1, y0.w, w2 * z0.w));
                split2(a, b, vh.y, vl.y);
            }
            {
                float a = fmaf(w0, x1.x, fmaf(w1, y1.x, w2 * z1.x));
                float b = fmaf(w0, x1.y, fmaf(w1, y1.y, w2 * z1.y));
                split2(a, b, vh.z, vl.z);
            }
            {
                float a = fmaf(w0, x1.z, fmaf(w1, y1.z, w2 * z1.z));
                float b = fmaf(w0, x1.w, fmaf(w1, y1.w, w2 * z1.w));
                split2(a, b, vh.w, vl.w);
            }
            *reinterpret_cast<uint4*>(smA_hi + r * PSTRIDE + lane * 4) = vh;
            *reinterpret_cast<uint4*>(smA_lo + r * PSTRIDE + lane * 4) = vl;

            x0 = nx0; x1 = nx1;
        }
    }
    __syncthreads();

    // ---------------- Phase 2: out[48x128] = mix @ W via HMMA + LDSM --------
    // warp w owns n-tiles {2w, 2w+1}; 3 row-tiles of 16. B double-buffered.
    {
        const int g = lane >> 2;       // 0..7
        const int t = lane & 3;        // 0..3

        const uint32_t a_base = (uint32_t)__cvta_generic_to_shared(smA_hi);
        const uint32_t l_base = (uint32_t)__cvta_generic_to_shared(smA_lo);
        const uint32_t lane_off =
            (uint32_t)((lane & 15) * PSTRIDE + 4 * (lane >> 4));  // u32 units

        float acc[3][2][4];
#pragma unroll
        for (int r = 0; r < 3; ++r)
#pragma unroll
            for (int c = 0; c < 2; ++c)
#pragma unroll
                for (int i = 0; i < 4; ++i) acc[r][c][i] = 0.f;

        // preload B fragments for s = 0
        uint2 bh[2], bl[2];
#pragma unroll
        for (int c = 0; c < 2; ++c) {
            int nt = 2 * w + c;
            bh[c] = __ldg(&g_Bhi[nt * 32 + lane]);
            bl[c] = __ldg(&g_Blo[nt * 32 + lane]);
        }

#pragma unroll 1
        for (int s = 0; s < 16; ++s) {
            // prefetch next s while this step's MMAs run
            uint2 nbh[2], nbl[2];
            if (s < 15) {
#pragma unroll
                for (int c = 0; c < 2; ++c) {
                    int nt = 2 * w + c;
                    nbh[c] = __ldg(&g_Bhi[((s + 1) * 16 + nt) * 32 + lane]);
                    nbl[c] = __ldg(&g_Blo[((s + 1) * 16 + nt) * 32 + lane]);
                }
            }

            uint32_t ah[3][4], al[3][4];
#pragma unroll
            for (int r = 0; r < 3; ++r) {
                uint32_t off = 4u * (16u * r * PSTRIDE + lane_off + 8u * s);
                ldsm_x4(ah[r], a_base + off);
                ldsm_x4(al[r], l_base + off);
            }
#pragma unroll
            for (int c = 0; c < 2; ++c) {
#pragma unroll
                for (int r = 0; r < 3; ++r) {
                    MMA_BF16(acc[r][c], ah[r], bh[c].x, bh[c].y);
                    MMA_BF16(acc[r][c], al[r], bh[c].x, bh[c].y);
                    MMA_BF16(acc[r][c], ah[r], bl[c].x, bl[c].y);
                }
            }
            if (s < 15) {
#pragma unroll
                for (int c = 0; c < 2; ++c) { bh[c] = nbh[c]; bl[c] = nbl[c]; }
            }
        }

        // epilogue: d0,d1 -> (row 16r+g, cols 2t,2t+1); d2,d3 -> row +8
#pragma unroll
        for (int r = 0; r < 3; ++r) {
            const long long rowA = (long long)(row0 + 16 * r + g);
            const long long rowB = rowA + 8;
            const bool vA = rowA < NROWS;
            const bool vB = rowB < NROWS;
#pragma unroll
            for (int c = 0; c < 2; ++c) {
                const int col = 8 * (2 * w + c) + 2 * t;
                if (vA) {
                    float2 v0 = make_float2(acc[r][c][0], acc[r][c][1]);
                    *reinterpret_cast<float2*>(out + rowA * OUT_F + col) = v0;
                }
                if (vB) {
                    float2 v1 = make_float2(acc[r][c][2], acc[r][c][3]);
                    *reinterpret_cast<float2*>(out + rowB * OUT_F + col) = v1;
                }
            }
        }
    }
}

// ---------------------------------------------------------------------------
extern "C" void kernel_launch(void* const* d_in, const int* in_sizes, int n_in,
                              void* d_out, int out_size) {
    const float* T  = (const float*)d_in[0];
    const float* O1 = (const float*)d_in[1];
    const float* O2 = (const float*)d_in[2];
    const float* W  = (const float*)d_in[3];
    const float* s  = (const float*)d_in[4];
    float* out = (float*)d_out;

    cudaFuncSetAttribute(fused_attention_kernel,
                         cudaFuncAttributeMaxDynamicSharedMemorySize, SMEM_BYTES);

    prep_kernel<<<40, 256>>>(W, s);
    fused_attention_kernel<<<NBLK, THREADS, SMEM_BYTES>>>(T, O1, O2, out);
}